// round 7
// baseline (speedup 1.0000x reference)
#include <cuda_runtime.h>
#include <cstdint>

#define BATCH 8
#define NPTS  8192
#define NS    2048
#define KNBR  32
#define TB    512
#define NWARP (TB / 32)      // 16
#define NBKT  16             // 3D cells: 4 x 2 x 2 (one per FPS warp)
#define CAP   576            // slots per warp (bucket capacity incl. pads)
#define PPT   18             // CAP/32 points per thread
#define NPAIR (PPT / 2)      // 9 packed pairs

// scratch
__device__ float    g_new_xyz[BATCH * NS * 3];
__device__ unsigned g_progress[BATCH];

__device__ __forceinline__ unsigned ld_acq(const unsigned* p) {
    unsigned v;
    asm volatile("ld.acquire.gpu.global.u32 %0, [%1];" : "=r"(v) : "l"(p) : "memory");
    return v;
}
__device__ __forceinline__ void st_rel(unsigned* p, unsigned v) {
    asm volatile("st.release.gpu.global.u32 [%0], %1;" :: "l"(p), "r"(v) : "memory");
}

// packed f32x2 helpers (two independent IEEE f32 ops per instruction)
__device__ __forceinline__ unsigned long long pk2(float lo, float hi) {
    unsigned long long r;
    asm("mov.b64 %0, {%1, %2};" : "=l"(r) : "f"(lo), "f"(hi));
    return r;
}
__device__ __forceinline__ void upk2(float& lo, float& hi, unsigned long long v) {
    asm("mov.b64 {%0, %1}, %2;" : "=f"(lo), "=f"(hi) : "l"(v));
}
__device__ __forceinline__ unsigned long long add2(unsigned long long a, unsigned long long b) {
    unsigned long long r;
    asm("add.rn.f32x2 %0, %1, %2;" : "=l"(r) : "l"(a), "l"(b));
    return r;
}
__device__ __forceinline__ unsigned long long mul2(unsigned long long a, unsigned long long b) {
    unsigned long long r;
    asm("mul.rn.f32x2 %0, %1, %2;" : "=l"(r) : "l"(a), "l"(b));
    return r;
}

extern "C" __global__ void reset_kernel() {
    if (threadIdx.x < BATCH) g_progress[threadIdx.x] = 0;
}

// ---------------------------------------------------------------------------
// Fused kernel. Blocks 0..7: FPS producer (one per batch), warp-per-3D-cell
// with exact skip pruning. Blocks 8..: warp-per-centroid ball query + MLP.
// ---------------------------------------------------------------------------
extern "C" __global__ void __launch_bounds__(TB, 1)
fused_kernel(const float* __restrict__ xyz,
             const float* __restrict__ w1, const float* __restrict__ b1,
             const float* __restrict__ w2, const float* __restrict__ b2,
             const float* __restrict__ w3, const float* __restrict__ b3,
             float* __restrict__ out)
{
    extern __shared__ float sm[];
    const int t    = threadIdx.x;
    const int lane = t & 31;
    const int w    = t >> 5;

    if (blockIdx.x < BATCH) {
        // ================= FPS producer =================
        __shared__ unsigned long long skey2[2][32];   // [parity][warp or pad]
        __shared__ int s_filled[NBKT];
        __shared__ int s_ovfcnt;

        float* sx   = sm;
        float* sy   = sm + NPTS;
        float* sz   = sm + 2 * NPTS;
        int*   perm = (int*)(sm + 3 * NPTS);          // NBKT*CAP = 9216 slots
        int*   ovf  = perm + NBKT * CAP;              // up to NPTS (worst case)

        const int b = blockIdx.x;
        const float* base = xyz + (size_t)b * NPTS * 3;

        if (t == 0) s_ovfcnt = 0;
        if (t < 64) {                                  // zero the pad slots
            int pp = t >> 5, ll = t & 31;
            if (ll >= NWARP) skey2[pp][ll] = 0ull;
        }

        // load coords
        for (int i = t; i < NPTS; i += TB) {
            sx[i] = base[i * 3 + 0];
            sy[i] = base[i * 3 + 1];
            sz[i] = base[i * 3 + 2];
        }
        __syncthreads();

        // ---- stable bucket scatter: warp 0, lane c owns 3D cell c ----
        // cell id = (yc*2 + zc)*4 + xc  (x-neighbors -> different SMSPs)
        if (w == 0 && lane < NBKT) {
            int cur = 0;
            for (int i = 0; i < NPTS; i++) {
                int xc = (int)(sx[i] * 4.0f); xc = (xc > 3) ? 3 : xc;
                int yc = (int)(sy[i] * 2.0f); yc = (yc > 1) ? 1 : yc;
                int zc = (int)(sz[i] * 2.0f); zc = (zc > 1) ? 1 : zc;
                int bkt = ((yc * 2 + zc) << 2) | xc;
                if (bkt == lane) {
                    if (cur < CAP) perm[lane * CAP + cur] = i;
                    else { int o = atomicAdd(&s_ovfcnt, 1); ovf[o] = i; }
                    cur++;
                }
            }
            s_filled[lane] = (cur < CAP) ? cur : CAP;
        }
        __syncthreads();
        // overflow redistribution (rare; foreign points only widen a warp's
        // bounding box -> less skipping, never incorrect)
        if (t == 0) {
            for (int j = 0; j < s_ovfcnt; j++) {
                for (int b2 = 0; b2 < NBKT; b2++) {
                    if (s_filled[b2] < CAP) {
                        perm[b2 * CAP + s_filled[b2]] = ovf[j];
                        s_filled[b2]++;
                        break;
                    }
                }
            }
        }
        __syncthreads();
        // pads: replicate the bucket's first point (same original index ->
        // argmax ties between pad and original resolve identically)
        if (w == 0 && lane < NBKT) {
            int f = s_filled[lane];
            int rep = (f > 0) ? perm[lane * CAP] : 0;
            for (; f < CAP; f++) perm[lane * CAP + f] = rep;
        }
        __syncthreads();

        // ---- per-warp register load + 3D bounds ----
        float fx[PPT], fy[PPT], fz[PPT], dd[PPT];
#pragma unroll
        for (int k = 0; k < PPT; k++) {
            int oi = perm[w * CAP + k * 32 + lane];
            fx[k] = sx[oi]; fy[k] = sy[oi]; fz[k] = sz[oi];
            dd[k] = 1e10f;
        }
        unsigned long long px2[NPAIR], py2[NPAIR], pz2[NPAIR];
#pragma unroll
        for (int p = 0; p < NPAIR; p++) {
            px2[p] = pk2(fx[2 * p], fx[2 * p + 1]);
            py2[p] = pk2(fy[2 * p], fy[2 * p + 1]);
            pz2[p] = pk2(fz[2 * p], fz[2 * p + 1]);
        }
        float mnx = fx[0], mxx = fx[0];
        float mny = fy[0], mxy = fy[0];
        float mnz = fz[0], mxz = fz[0];
#pragma unroll
        for (int k = 1; k < PPT; k++) {
            mnx = fminf(mnx, fx[k]); mxx = fmaxf(mxx, fx[k]);
            mny = fminf(mny, fy[k]); mxy = fmaxf(mxy, fy[k]);
            mnz = fminf(mnz, fz[k]); mxz = fmaxf(mxz, fz[k]);
        }
        // coords >= 0 -> float bits are order-preserving as ints
        float xlo = __int_as_float(__reduce_min_sync(0xffffffffu, __float_as_int(mnx)));
        float xhi = __int_as_float(__reduce_max_sync(0xffffffffu, __float_as_int(mxx)));
        float ylo = __int_as_float(__reduce_min_sync(0xffffffffu, __float_as_int(mny)));
        float yhi = __int_as_float(__reduce_max_sync(0xffffffffu, __float_as_int(mxy)));
        float zlo = __int_as_float(__reduce_min_sync(0xffffffffu, __float_as_int(mnz)));
        float zhi = __int_as_float(__reduce_max_sync(0xffffffffu, __float_as_int(mxz)));

        int mb = __float_as_int(1e10f);   // cached warp-max (forces active at s=0)
        int wi = 0;                       // cached warp argmax (original idx)
        int far = 0;
        float* out_xyz = out + (size_t)b * 3 * NS;
        float* gx      = g_new_xyz + (size_t)b * NS * 3;

        for (int s = 0; s < NS; s++) {
            const int par = s & 1;
            float cx = sx[far], cy = sy[far], cz = sz[far];
            if (t == 0) {
                out_xyz[0 * NS + s] = cx;
                out_xyz[1 * NS + s] = cy;
                out_xyz[2 * NS + s] = cz;
                gx[s * 3 + 0] = cx; gx[s * 3 + 1] = cy; gx[s * 3 + 2] = cz;
                if ((s & 15) == 15) st_rel(&g_progress[b], (unsigned)(s + 1));
            }

            // exact skip: min squared distance from c to the warp's bounding
            // box (with margin) > warp max dd  =>  no dd can change.
            float Bw  = __int_as_float(mb);
            float dxi = fmaxf(fmaxf(xlo - cx, cx - xhi), 0.0f);
            float dyi = fmaxf(fmaxf(ylo - cy, cy - yhi), 0.0f);
            float dzi = fmaxf(fmaxf(zlo - cz, cz - zhi), 0.0f);
            float boxd = dxi * dxi + dyi * dyi + dzi * dzi;
            if (boxd <= Bw * 1.00001f) {
                // active: full distance update + argmax
                unsigned long long ncx = pk2(-cx, -cx);
                unsigned long long ncy = pk2(-cy, -cy);
                unsigned long long ncz = pk2(-cz, -cz);
                float bv   = -1.0f;
                int   slot = 0;
#pragma unroll
                for (int p = 0; p < NPAIR; p++) {
                    unsigned long long dx = add2(px2[p], ncx);
                    unsigned long long dy = add2(py2[p], ncy);
                    unsigned long long dz = add2(pz2[p], ncz);
                    dx = mul2(dx, dx);
                    dy = mul2(dy, dy);
                    dz = mul2(dz, dz);
                    unsigned long long d2 = add2(add2(dx, dy), dz); // (x2+y2)+z2
                    float dlo, dhi;
                    upk2(dlo, dhi, d2);
                    float n0 = fminf(dd[2 * p + 0], dlo); dd[2 * p + 0] = n0;
                    float n1 = fminf(dd[2 * p + 1], dhi); dd[2 * p + 1] = n1;
                    // ascending slot = ascending original idx (stable scatter):
                    // strict > keeps lowest original index on ties
                    if (n0 > bv) { bv = n0; slot = 2 * p + 0; }
                    if (n1 > bv) { bv = n1; slot = 2 * p + 1; }
                }
                int oidx = perm[w * CAP + slot * 32 + lane];
                int fb = __float_as_int(bv);
                mb = __reduce_max_sync(0xffffffffu, fb);
                int ca = (fb == mb) ? oidx : 0x7fffffff;
                wi = __reduce_min_sync(0xffffffffu, ca);
            }
            if (lane == 0) {
                skey2[par][w] =
                    ((unsigned long long)(unsigned)mb << 32) | (unsigned)(~wi);
            }
            __syncthreads();
            // combine all 16 warp winners (+16 zero pads) in every warp
            unsigned long long kk = skey2[par][lane];
            int      hi = (int)(kk >> 32);
            unsigned lo = (unsigned)kk;
            int m2 = __reduce_max_sync(0xffffffffu, hi);
            unsigned cand = (hi == m2) ? lo : 0u;
            unsigned mi = __reduce_max_sync(0xffffffffu, cand);
            far = (int)(~mi);
        }
        if (t == 0) st_rel(&g_progress[b], (unsigned)NS);
    } else {
        // ================= MLP consumer =================
        float* w1s = sm;              // 64x3
        float* b1s = w1s + 192;       // 64
        float* w2t = b1s + 64;        // 64x64 transposed [c][o]
        float* b2s = w2t + 4096;      // 64
        float* w3s = b2s + 64;        // 128x64 row-major [o][c]
        float* b3s = w3s + 8192;      // 128
        int*   lists = (int*)(b3s + 128);  // NWARP * 32

        for (int i = t; i < 192; i += TB) w1s[i] = w1[i];
        if (t < 64) { b1s[t] = b1[t]; b2s[t] = b2[t]; }
        for (int i = t; i < 4096; i += TB) {
            int o = i >> 6, c = i & 63;
            w2t[c * 64 + o] = w2[i];
        }
        for (int i = t; i < 8192; i += TB) w3s[i] = w3[i];
        if (t < 128) b3s[t] = b3[t];

        // block mapping: batch b, s range [sbase, sbase+16)
        const int idx   = blockIdx.x - BATCH;      // 0..1023
        const int b     = idx & 7;
        const int sbase = (idx >> 3) * NWARP;
        const int s     = sbase + w;

        // single poller per block, coarse gate on the whole block's range
        if (t == 0) {
            unsigned need = (unsigned)(sbase + NWARP);
            while (ld_acq(&g_progress[b]) < need) __nanosleep(2048);
        }
        __syncthreads();

        const float* xb   = xyz + (size_t)b * NPTS * 3;
        const float* cptr = g_new_xyz + ((size_t)b * NS + s) * 3;
        const float cx = cptr[0], cy = cptr[1], cz = cptr[2];

        // --- ball query: first KNBR points (ascending idx) with d2 <= r^2 ---
        int* list = lists + w * KNBR;
        int  cnt  = 0;
        for (int basei = 0; basei < NPTS; basei += 32) {
            int pi = basei + lane;
            float x = xb[pi * 3 + 0];
            float y = xb[pi * 3 + 1];
            float z = xb[pi * 3 + 2];
            float dx = __fsub_rn(x, cx);
            float dy = __fsub_rn(y, cy);
            float dz = __fsub_rn(z, cz);
            float d  = __fadd_rn(__fadd_rn(__fmul_rn(dx, dx), __fmul_rn(dy, dy)),
                                 __fmul_rn(dz, dz));
            bool within = (d <= 0.04f);
            unsigned m  = __ballot_sync(0xffffffffu, within);
            if (within) {
                int pos = cnt + __popc(m & ((1u << lane) - 1u));
                if (pos < KNBR) list[pos] = pi;
            }
            cnt += __popc(m);
            if (cnt >= KNBR) break;
        }
        __syncwarp();
        const int nb = list[(lane < cnt) ? lane : 0];

        const float rx = xb[nb * 3 + 0] - cx;
        const float ry = xb[nb * 3 + 1] - cy;
        const float rz = xb[nb * 3 + 2] - cz;

        // --- layer1 fused into layer2 accumulation ---
        float h2[64];
#pragma unroll
        for (int o = 0; o < 64; o++) h2[o] = b2s[o];

        for (int c = 0; c < 64; c++) {
            float a = fmaf(rx, w1s[c * 3 + 0], b1s[c]);
            a = fmaf(ry, w1s[c * 3 + 1], a);
            a = fmaf(rz, w1s[c * 3 + 2], a);
            float hv = fmaxf(a, 0.0f);
            const float4* row = (const float4*)(w2t + c * 64);
#pragma unroll
            for (int o4 = 0; o4 < 16; o4++) {
                float4 wv = row[o4];
                h2[o4 * 4 + 0] = fmaf(hv, wv.x, h2[o4 * 4 + 0]);
                h2[o4 * 4 + 1] = fmaf(hv, wv.y, h2[o4 * 4 + 1]);
                h2[o4 * 4 + 2] = fmaf(hv, wv.z, h2[o4 * 4 + 2]);
                h2[o4 * 4 + 3] = fmaf(hv, wv.w, h2[o4 * 4 + 3]);
            }
        }
#pragma unroll
        for (int o = 0; o < 64; o++) h2[o] = fmaxf(h2[o], 0.0f);

        // --- layer3 + relu + warp max-pool ---
        float* outb = out + (size_t)BATCH * 3 * NS + (size_t)b * 128 * NS + s;
        for (int o = 0; o < 128; o++) {
            float a = b3s[o];
            const float4* row = (const float4*)(w3s + o * 64);
#pragma unroll
            for (int c4 = 0; c4 < 16; c4++) {
                float4 wv = row[c4];
                a = fmaf(h2[c4 * 4 + 0], wv.x, a);
                a = fmaf(h2[c4 * 4 + 1], wv.y, a);
                a = fmaf(h2[c4 * 4 + 2], wv.z, a);
                a = fmaf(h2[c4 * 4 + 3], wv.w, a);
            }
            a = fmaxf(a, 0.0f);
#pragma unroll
            for (int off = 16; off; off >>= 1)
                a = fmaxf(a, __shfl_xor_sync(0xffffffffu, a, off));
            if (lane == 0) outb[(size_t)o * NS] = a;
        }
    }
}

// ---------------------------------------------------------------------------
extern "C" void kernel_launch(void* const* d_in, const int* in_sizes, int n_in,
                              void* d_out, int out_size)
{
    const float* xyz = (const float*)d_in[0];
    const float* w1 = (const float*)d_in[2];
    const float* b1 = (const float*)d_in[3];
    const float* w2 = (const float*)d_in[4];
    const float* b2 = (const float*)d_in[5];
    const float* w3 = (const float*)d_in[6];
    const float* b3 = (const float*)d_in[7];

    float* out = (float*)d_out;

    // FPS layout: coords 96KB + perm 36KB + ovf 32KB
    const int smem = 3 * NPTS * (int)sizeof(float)
                   + (NBKT * CAP) * (int)sizeof(int)
                   + NPTS * (int)sizeof(int) + 256;
    cudaFuncSetAttribute(fused_kernel,
                         cudaFuncAttributeMaxDynamicSharedMemorySize, smem);

    const int nmlp = (BATCH * NS) / NWARP;       // 1024 consumer blocks
    reset_kernel<<<1, 32>>>();
    fused_kernel<<<BATCH + nmlp, TB, smem>>>(xyz, w1, b1, w2, b2, w3, b3, out);
}